// round 8
// baseline (speedup 1.0000x reference)
#include <cuda_runtime.h>
#include <cstdint>

// Problem constants: N=65536, D_LAT=64, K=64, D_DATA=512
#define KC      64
#define DL      64
#define RPT     128              // rows per subtile
#define NSUB    2
#define RPB     (RPT * NSUB)     // 256 rows per CTA
#define NTH     256              // 8 warps
#define NIT     10
#define ALPHA_C 0.001f
#define EPS_C   1e-8f
#define POS_INF_F (__int_as_float(0x7f800000))

// smem float offsets
#define XS_STR  76               // 64 data + ones col(64) + zero pad 65..71
#define OFF_XS  0
#define OFF_RS  (OFF_XS + RPT * XS_STR)         // 9728
#define OFF_CF  (OFF_RS + RPT * XS_STR)         // 19456: C fragment layout, 4096 floats
#define OFF_C2  (OFF_CF + 4096)                 // 23552
#define OFF_X2  (OFF_C2 + KC)                   // 23616
#define SMEM_FLOATS (OFF_X2 + RPT)              // 23744
#define SMEM_BYTES (SMEM_FLOATS * 4)            // 94976 B -> 2 CTAs/SM

// Per-iteration accumulation buffers (iter t writes buf t, iter t+1 reads it)
__device__ float g_S[(NIT - 1) * KC * DL];
__device__ float g_rsum[(NIT - 1) * KC];
__device__ float g_loss;
__device__ float g_dec;
__device__ int   g_bar;

// ---------------------------------------------------------------------------
// tf32 truncation mask (what the mma hardware keeps from an f32 register)
__device__ __forceinline__ float truncf32(float x) {
    return __uint_as_float(__float_as_uint(x) & 0xFFFFE000u);
}

// D (f32) += A (tf32-in-f32-regs) * B, m16n8k8
__device__ __forceinline__ void mma_tf32(float* d, const uint32_t* a, uint32_t b0, uint32_t b1) {
    asm volatile(
        "mma.sync.aligned.m16n8k8.row.col.f32.tf32.tf32.f32 "
        "{%0,%1,%2,%3}, {%4,%5,%6,%7}, {%8,%9}, {%0,%1,%2,%3};"
        : "+f"(d[0]), "+f"(d[1]), "+f"(d[2]), "+f"(d[3])
        : "r"(a[0]), "r"(a[1]), "r"(a[2]), "r"(a[3]), "r"(b0), "r"(b1));
}

// ---------------------------------------------------------------------------
__global__ void init_kernel() {
    int t = blockIdx.x * blockDim.x + threadIdx.x;
    int total = (NIT - 1) * KC * DL;
    for (int i = t; i < total; i += gridDim.x * blockDim.x) g_S[i] = 0.0f;
    if (t < (NIT - 1) * KC) g_rsum[t] = 0.0f;
    if (t == 0) { g_loss = 0.0f; g_dec = 0.0f; g_bar = 0; }
}

// ---------------------------------------------------------------------------
// Persistent fused kernel: 10 soft-kmeans iterations + decoder loss,
// grid barrier between iterations hidden behind the decoder stream.
// ---------------------------------------------------------------------------
extern __shared__ float sf[];

__global__ __launch_bounds__(NTH, 2)
void main_kernel(float* __restrict__ out,
                 const float* __restrict__ enc,
                 const float4* __restrict__ X4, const float4* __restrict__ D4,
                 int n4, int chunk, int N) {
    uint32_t* su = (uint32_t*)sf;
    float* xs  = sf + OFF_XS;   uint32_t* xsu = su + OFF_XS;
    uint32_t* rsu = su + OFF_RS;
    float2* cf = (float2*)(sf + OFF_CF);    // [(k*8+n)*32 + lane] = (b0,b1)
    float* c2s = sf + OFF_C2;
    float* x2s = sf + OFF_X2;

    const int tid  = threadIdx.x;
    const int wid  = tid >> 5;
    const int lane = tid & 31;
    const int g    = lane >> 2;     // groupID
    const int tg   = lane & 3;      // threadID_in_group
    const int mg = wid & 3, nh = wid >> 2;
    const int nbase = nh * 4, ntiles = nh ? 5 : 4;
    const int row_base = blockIdx.x * RPB;
    const int nct = gridDim.x;

    int bar_target = 0;

    for (int it = 0; it < NIT; it++) {
        const bool last = (it == NIT - 1);

        // --- C setup: C[j][d] from prev-iter S/rsum (or enc rows for it=0),
        //     B-fragment pair layout; c2 from truncated values ---
        {
            const int j = tid >> 2, h = tid & 3;   // 16 cols per thread
            const int n = j >> 3, gg = j & 7;      // j = 8n + gg
            float part = 0.0f;
            float invd = 0.0f;
            if (it > 0) invd = 1.0f / (__ldcg(&g_rsum[(it - 1) * KC + j]) + EPS_C);
            const float* src = (it == 0) ? (enc + j * DL) : (g_S + (it - 1) * KC * DL + j * DL);
            float v[16];
            #pragma unroll
            for (int c = 0; c < 16; c++) {
                float x = (it == 0) ? src[16 * h + c] : __ldcg(src + 16 * h + c);
                if (it > 0) x *= invd;
                x = truncf32(x);
                part += x * x;
                v[c] = x;
            }
            #pragma unroll
            for (int kk = 0; kk < 2; kk++) {
                const int k = 2 * h + kk;
                #pragma unroll
                for (int t = 0; t < 4; t++) {
                    float2 p = make_float2(v[8 * kk + t], v[8 * kk + t + 4]);
                    cf[(k * 8 + n) * 32 + 4 * gg + t] = p;
                }
            }
            part += __shfl_xor_sync(0xffffffffu, part, 1);
            part += __shfl_xor_sync(0xffffffffu, part, 2);
            if (h == 0) c2s[j] = part;
        }

        // GEMM2 accumulators
        float sfr[5][4];
        #pragma unroll
        for (int n = 0; n < 5; n++)
            #pragma unroll
            for (int q = 0; q < 4; q++) sfr[n][q] = 0.0f;

        float lossacc = 0.0f;

        for (int s = 0; s < NSUB; s++) {
            const int row0 = row_base + s * RPT;
            __syncthreads();   // cf/c2 ready; xs/rs free

            // --- load x rows (2 threads per row), truncate, x2 ---
            {
                const int row = tid >> 1, half = tid & 1;
                const float4* rowp = (const float4*)(enc + (size_t)(row0 + row) * DL) + 8 * half;
                float x2 = 0.0f;
                #pragma unroll
                for (int q = 0; q < 8; q++) {
                    float4 v = rowp[q];
                    v.x = truncf32(v.x); v.y = truncf32(v.y);
                    v.z = truncf32(v.z); v.w = truncf32(v.w);
                    x2 += v.x * v.x + v.y * v.y;
                    x2 += v.z * v.z + v.w * v.w;
                    *(float4*)(xs + row * XS_STR + 32 * half + 4 * q) = v;
                }
                x2 += __shfl_xor_sync(0xffffffffu, x2, 1);
                if (half == 0) {
                    x2s[row] = x2;
                } else {
                    xs[row * XS_STR + 64] = 1.0f;      // ones column -> rsum via GEMM2
                    #pragma unroll
                    for (int c = 65; c < 72; c++) xs[row * XS_STR + c] = 0.0f;
                }
            }
            __syncthreads();

            // --- GEMM1: warp's D[16x64] = x[16x64] @ C^T ---
            const int wr0 = wid * 16;
            float dfr[8][4];
            #pragma unroll
            for (int n = 0; n < 8; n++)
                #pragma unroll
                for (int q = 0; q < 4; q++) dfr[n][q] = 0.0f;

            #pragma unroll
            for (int k = 0; k < 8; k++) {
                uint32_t afr[4];
                afr[0] = xsu[(wr0 + g) * XS_STR + 8 * k + tg];
                afr[1] = xsu[(wr0 + g + 8) * XS_STR + 8 * k + tg];
                afr[2] = xsu[(wr0 + g) * XS_STR + 8 * k + tg + 4];
                afr[3] = xsu[(wr0 + g + 8) * XS_STR + 8 * k + tg + 4];
                #pragma unroll
                for (int n = 0; n < 8; n++) {
                    float2 b = cf[(k * 8 + n) * 32 + lane];
                    mma_tf32(dfr[n], afr, __float_as_uint(b.x), __float_as_uint(b.y));
                }
            }

            // --- epilogue: d2, softmax, write r (or loss) ---
            float c2v[16];
            {
                const float2* c2p = (const float2*)(c2s);
                #pragma unroll
                for (int n = 0; n < 8; n++) {
                    float2 p = c2p[4 * n + tg];
                    c2v[2 * n] = p.x; c2v[2 * n + 1] = p.y;
                }
            }
            #pragma unroll
            for (int h = 0; h < 2; h++) {
                const int lr = wr0 + 8 * h + g;
                const float x2v = x2s[lr];
                float d2v[16];
                float mn = POS_INF_F;
                #pragma unroll
                for (int n = 0; n < 8; n++) {
                    float v0 = fmaxf(x2v + c2v[2 * n]     - 2.0f * dfr[n][2 * h],     0.0f);
                    float v1 = fmaxf(x2v + c2v[2 * n + 1] - 2.0f * dfr[n][2 * h + 1], 0.0f);
                    d2v[2 * n] = v0; d2v[2 * n + 1] = v1;
                    mn = fminf(mn, fminf(v0, v1));
                }
                mn = fminf(mn, __shfl_xor_sync(0xffffffffu, mn, 1));
                mn = fminf(mn, __shfl_xor_sync(0xffffffffu, mn, 2));
                float Z = 0.0f, ed2 = 0.0f;
                float ev[16];
                #pragma unroll
                for (int q = 0; q < 16; q++) {
                    float e = __expf(mn - d2v[q]);
                    Z += e; ed2 += e * d2v[q];
                    ev[q] = e;
                }
                Z += __shfl_xor_sync(0xffffffffu, Z, 1);
                Z += __shfl_xor_sync(0xffffffffu, Z, 2);
                const float inv = 1.0f / Z;
                if (last) {
                    ed2 += __shfl_xor_sync(0xffffffffu, ed2, 1);
                    ed2 += __shfl_xor_sync(0xffffffffu, ed2, 2);
                    lossacc += 0.25f * ed2 * inv;   // quad holds 4 copies
                } else {
                    #pragma unroll
                    for (int n = 0; n < 8; n++) {
                        rsu[lr * XS_STR + 8 * n + 2 * tg]     = __float_as_uint(ev[2 * n] * inv);
                        rsu[lr * XS_STR + 8 * n + 2 * tg + 1] = __float_as_uint(ev[2 * n + 1] * inv);
                    }
                }
            }

            if (!last) {
                __syncthreads();   // rs complete
                // --- GEMM2: S[64x72] += r^T[64x128] @ xext[128x72] ---
                const int j0 = 16 * mg;
                #pragma unroll
                for (int kk = 0; kk < 16; kk++) {
                    uint32_t afr[4];
                    afr[0] = rsu[(8 * kk + tg) * XS_STR + j0 + g];
                    afr[1] = rsu[(8 * kk + tg) * XS_STR + j0 + g + 8];
                    afr[2] = rsu[(8 * kk + tg + 4) * XS_STR + j0 + g];
                    afr[3] = rsu[(8 * kk + tg + 4) * XS_STR + j0 + g + 8];
                    #pragma unroll
                    for (int n = 0; n < 5; n++) {
                        if (n < ntiles) {
                            uint32_t b0 = xsu[(8 * kk + tg) * XS_STR + 8 * (nbase + n) + g];
                            uint32_t b1 = xsu[(8 * kk + tg + 4) * XS_STR + 8 * (nbase + n) + g];
                            mma_tf32(sfr[n], afr, b0, b1);
                        }
                    }
                }
            }
        }

        if (!last) {
            // GEMM2 epilogue: atomics to g_S / g_rsum
            float* gs = g_S + it * KC * DL;
            const int j0 = 16 * mg;
            #pragma unroll
            for (int h = 0; h < 2; h++) {
                const int j = j0 + g + 8 * h;
                #pragma unroll
                for (int n = 0; n < 5; n++) {
                    const int nn = nbase + n;
                    if (n < ntiles && nn < 8) {
                        atomicAdd(&gs[j * DL + 8 * nn + 2 * tg],     sfr[n][2 * h]);
                        atomicAdd(&gs[j * DL + 8 * nn + 2 * tg + 1], sfr[n][2 * h + 1]);
                    }
                }
                if (nh == 1 && tg == 0)   // n==8: ones column = rsum
                    atomicAdd(&g_rsum[it * KC + j], sfr[4][2 * h]);
            }
        } else {
            float v = lossacc;
            #pragma unroll
            for (int o = 16; o > 0; o >>= 1) v += __shfl_down_sync(0xffffffffu, v, o);
            if (lane == 0) atomicAdd(&g_loss, v);
        }

        // --- publish + arrive ---
        __threadfence();
        bar_target += nct;
        if (tid == 0) atomicAdd(&g_bar, 1);

        // --- decoder chunk for this iteration (streaming, hides barrier wait) ---
        {
            const int ds = it * chunk;
            const int de = (ds + chunk < n4) ? ds + chunk : n4;
            float acc = 0.0f;
            const int stride = nct * NTH;
            for (int i = ds + blockIdx.x * NTH + tid; i < de; i += stride) {
                float4 x = __ldcs(&X4[i]), d = __ldcs(&D4[i]);
                float a = x.x - d.x, b = x.y - d.y, c = x.z - d.z, e = x.w - d.w;
                acc += a * a + b * b;
                acc += c * c + e * e;
            }
            #pragma unroll
            for (int o = 16; o > 0; o >>= 1) acc += __shfl_down_sync(0xffffffffu, acc, o);
            if (lane == 0) atomicAdd(&g_dec, acc);
        }

        // --- spin until all CTAs arrived for this iteration ---
        if (tid == 0) {
            volatile int* vb = &g_bar;
            while (*vb < bar_target) __nanosleep(128);
        }
        __syncthreads();
    }

    // final arrival covering the last decoder chunk + loss
    __threadfence();
    if (tid == 0) atomicAdd(&g_bar, 1);
    if (blockIdx.x == 0 && tid == 0) {
        volatile int* vb = &g_bar;
        const int tgt = (NIT + 1) * nct;
        while (*vb < tgt) __nanosleep(128);
        float dec = __ldcg(&g_dec);
        float cl  = __ldcg(&g_loss);
        out[0] = dec / (float)(4 * (size_t)n4) + ALPHA_C * (cl / (float)N);
    }
}

// ---------------------------------------------------------------------------
extern "C" void kernel_launch(void* const* d_in, const int* in_sizes, int n_in,
                              void* d_out, int out_size) {
    const float* X   = (const float*)d_in[0];
    const float* enc = (const float*)d_in[1];
    const float* dec = (const float*)d_in[2];
    const int nX = in_sizes[0];
    const int N  = in_sizes[1] / DL;
    const int n4 = nX / 4;

    cudaFuncSetAttribute(main_kernel, cudaFuncAttributeMaxDynamicSharedMemorySize, SMEM_BYTES);

    init_kernel<<<40, 1024>>>();

    const int blocks = N / RPB;   // 256 <= 296 resident slots at 2 CTAs/SM: single wave
    const int chunk = (n4 + NIT - 1) / NIT;
    main_kernel<<<blocks, NTH, SMEM_BYTES>>>(
        (float*)d_out, enc, (const float4*)X, (const float4*)dec, n4, chunk, N);
}

// round 11
// speedup vs baseline: 1.0702x; 1.0702x over previous
#include <cuda_runtime.h>
#include <cstdint>

// Problem constants: N=65536, D_LAT=64, K=64, D_DATA=512
#define KC      64
#define DL      64
#define RPT     128              // rows per subtile
#define NSUB    2
#define RPB     (RPT * NSUB)     // 256 rows per CTA
#define NTH     256              // 8 warps
#define NIT     10
#define ALPHA_C 0.001f
#define EPS_C   1e-8f
#define POS_INF_F (__int_as_float(0x7f800000))

// smem float offsets
#define XS_STR  76               // 64 data + ones col(64) + zero pad 65..71
#define OFF_XS  0
#define OFF_RS  (OFF_XS + RPT * XS_STR)         // 9728
#define OFF_CF  (OFF_RS + RPT * XS_STR)         // 19456: C fragment layout, 4096 floats
#define OFF_C2  (OFF_CF + 4096)                 // 23552
#define OFF_X2  (OFF_C2 + KC)                   // 23616
#define OFF_RED (OFF_X2 + RPT)                  // 23744
#define SMEM_FLOATS (OFF_RED + 32)
#define SMEM_BYTES (SMEM_FLOATS * 4)            // 95104 B -> 2 CTAs/SM

// Per-iteration accumulation buffers (iter t writes buf t, iter t+1 reads it)
__device__ float g_S[(NIT - 1) * KC * DL];
__device__ float g_rsum[(NIT - 1) * KC];
__device__ float g_loss;
__device__ float g_dec;

// ---------------------------------------------------------------------------
// tf32 truncation mask (what the mma hardware keeps from an f32 register)
__device__ __forceinline__ float truncf32(float x) {
    return __uint_as_float(__float_as_uint(x) & 0xFFFFE000u);
}

// D (f32) += A (tf32-in-f32-regs) * B, m16n8k8
__device__ __forceinline__ void mma_tf32(float* d, const uint32_t* a, uint32_t b0, uint32_t b1) {
    asm volatile(
        "mma.sync.aligned.m16n8k8.row.col.f32.tf32.tf32.f32 "
        "{%0,%1,%2,%3}, {%4,%5,%6,%7}, {%8,%9}, {%0,%1,%2,%3};"
        : "+f"(d[0]), "+f"(d[1]), "+f"(d[2]), "+f"(d[3])
        : "r"(a[0]), "r"(a[1]), "r"(a[2]), "r"(a[3]), "r"(b0), "r"(b1));
}

// ---------------------------------------------------------------------------
__global__ void init_kernel() {
    int t = blockIdx.x * blockDim.x + threadIdx.x;
    int total = (NIT - 1) * KC * DL;
    for (int i = t; i < total; i += gridDim.x * blockDim.x) g_S[i] = 0.0f;
    if (t < (NIT - 1) * KC) g_rsum[t] = 0.0f;
    if (t == 0) { g_loss = 0.0f; g_dec = 0.0f; }
}

// ---------------------------------------------------------------------------
// Main fused iteration kernel (mma.sync tf32) + decoder-loss chunk
// ---------------------------------------------------------------------------
extern __shared__ float sf[];

__global__ __launch_bounds__(NTH, 2)
void main_kernel(const float* __restrict__ enc,
                 const float4* __restrict__ X4, const float4* __restrict__ D4,
                 int d_start, int d_end, int N, int it) {
    uint32_t* su = (uint32_t*)sf;
    float* xs  = sf + OFF_XS;   uint32_t* xsu = su + OFF_XS;
    uint32_t* rsu = su + OFF_RS;
    float2* cf = (float2*)(sf + OFF_CF);    // [(k*8+n)*32 + lane] = (b0,b1)
    float* c2s = sf + OFF_C2;
    float* x2s = sf + OFF_X2;
    float* red = sf + OFF_RED;

    const int tid  = threadIdx.x;
    const int wid  = tid >> 5;
    const int lane = tid & 31;
    const int g    = lane >> 2;     // groupID
    const int tg   = lane & 3;      // threadID_in_group
    const bool last = (it == NIT - 1);
    const int row_base = blockIdx.x * RPB;

    // --- C setup: C[j][d] from prev-iter S/rsum (or enc rows for it=0),
    //     written in B-fragment pair layout; c2 from truncated values ---
    {
        const int j = tid >> 2, h = tid & 3;   // 16 cols per thread: cols 16h..16h+15
        const int n = j >> 3, gg = j & 7;      // j = 8n + gg
        float part = 0.0f;
        float invd = 0.0f;
        if (it > 0) invd = 1.0f / (g_rsum[(it - 1) * KC + j] + EPS_C);
        const float* src = (it == 0) ? (enc + j * DL) : (g_S + (it - 1) * KC * DL + j * DL);
        float v[16];
        #pragma unroll
        for (int c = 0; c < 16; c++) {
            float x = src[16 * h + c];
            if (it > 0) x *= invd;
            x = truncf32(x);
            part += x * x;
            v[c] = x;
        }
        // k values covered: k = 2h, 2h+1; pairs (col 8k+t, col 8k+t+4)
        #pragma unroll
        for (int kk = 0; kk < 2; kk++) {
            const int k = 2 * h + kk;
            #pragma unroll
            for (int t = 0; t < 4; t++) {
                float2 p = make_float2(v[8 * kk + t], v[8 * kk + t + 4]);
                cf[(k * 8 + n) * 32 + 4 * gg + t] = p;
            }
        }
        part += __shfl_xor_sync(0xffffffffu, part, 1);
        part += __shfl_xor_sync(0xffffffffu, part, 2);
        if (h == 0) c2s[j] = part;
    }

    // GEMM2 accumulators: warp (mg = wid&3, nh = wid>>2)
    const int mg = wid & 3, nh = wid >> 2;
    const int nbase = nh * 4, ntiles = nh ? 5 : 4;
    float sfr[5][4];
    #pragma unroll
    for (int n = 0; n < 5; n++)
        #pragma unroll
        for (int q = 0; q < 4; q++) sfr[n][q] = 0.0f;

    float lossacc = 0.0f;

    for (int s = 0; s < NSUB; s++) {
        const int row0 = row_base + s * RPT;
        __syncthreads();   // Cs ready (s=0); xs/rs free from prev subtile (s>0)

        // --- load x rows (2 threads per row), truncate, x2 ---
        {
            const int row = tid >> 1, half = tid & 1;
            const float4* rowp = (const float4*)(enc + (size_t)(row0 + row) * DL) + 8 * half;
            float x2 = 0.0f;
            #pragma unroll
            for (int q = 0; q < 8; q++) {
                float4 v = rowp[q];
                v.x = truncf32(v.x); v.y = truncf32(v.y);
                v.z = truncf32(v.z); v.w = truncf32(v.w);
                x2 += v.x * v.x + v.y * v.y;
                x2 += v.z * v.z + v.w * v.w;
                *(float4*)(xs + row * XS_STR + 32 * half + 4 * q) = v;
            }
            x2 += __shfl_xor_sync(0xffffffffu, x2, 1);
            if (half == 0) {
                x2s[row] = x2;
            } else {
                xs[row * XS_STR + 64] = 1.0f;      // ones column -> rsum via GEMM2
                #pragma unroll
                for (int c = 65; c < 72; c++) xs[row * XS_STR + c] = 0.0f;
            }
        }
        __syncthreads();

        // --- GEMM1: warp's D[16x64] = x[16x64] @ C^T, k-outer, B from frag layout ---
        const int wr0 = wid * 16;
        float dfr[8][4];
        #pragma unroll
        for (int n = 0; n < 8; n++)
            #pragma unroll
            for (int q = 0; q < 4; q++) dfr[n][q] = 0.0f;

        #pragma unroll
        for (int k = 0; k < 8; k++) {
            uint32_t afr[4];
            afr[0] = xsu[(wr0 + g) * XS_STR + 8 * k + tg];
            afr[1] = xsu[(wr0 + g + 8) * XS_STR + 8 * k + tg];
            afr[2] = xsu[(wr0 + g) * XS_STR + 8 * k + tg + 4];
            afr[3] = xsu[(wr0 + g + 8) * XS_STR + 8 * k + tg + 4];
            #pragma unroll
            for (int n = 0; n < 8; n++) {
                float2 b = cf[(k * 8 + n) * 32 + lane];
                mma_tf32(dfr[n], afr, __float_as_uint(b.x), __float_as_uint(b.y));
            }
        }

        // --- epilogue: d2, softmax, write r (or loss) ---
        float c2v[16];
        {
            const float2* c2p = (const float2*)(c2s);
            #pragma unroll
            for (int n = 0; n < 8; n++) {
                float2 p = c2p[4 * n + tg];
                c2v[2 * n] = p.x; c2v[2 * n + 1] = p.y;
            }
        }
        #pragma unroll
        for (int h = 0; h < 2; h++) {
            const int lr = wr0 + 8 * h + g;
            const float x2v = x2s[lr];
            float d2v[16];
            float mn = POS_INF_F;
            #pragma unroll
            for (int n = 0; n < 8; n++) {
                float v0 = fmaxf(x2v + c2v[2 * n]     - 2.0f * dfr[n][2 * h],     0.0f);
                float v1 = fmaxf(x2v + c2v[2 * n + 1] - 2.0f * dfr[n][2 * h + 1], 0.0f);
                d2v[2 * n] = v0; d2v[2 * n + 1] = v1;
                mn = fminf(mn, fminf(v0, v1));
            }
            mn = fminf(mn, __shfl_xor_sync(0xffffffffu, mn, 1));
            mn = fminf(mn, __shfl_xor_sync(0xffffffffu, mn, 2));
            float Z = 0.0f, ed2 = 0.0f;
            float ev[16];
            #pragma unroll
            for (int q = 0; q < 16; q++) {
                float e = __expf(mn - d2v[q]);
                Z += e; ed2 += e * d2v[q];
                ev[q] = e;
            }
            Z += __shfl_xor_sync(0xffffffffu, Z, 1);
            Z += __shfl_xor_sync(0xffffffffu, Z, 2);
            const float inv = 1.0f / Z;
            if (last) {
                ed2 += __shfl_xor_sync(0xffffffffu, ed2, 1);
                ed2 += __shfl_xor_sync(0xffffffffu, ed2, 2);
                lossacc += 0.25f * ed2 * inv;   // quad holds 4 copies
            } else {
                #pragma unroll
                for (int n = 0; n < 8; n++) {
                    rsu[lr * XS_STR + 8 * n + 2 * tg]     = __float_as_uint(ev[2 * n] * inv);
                    rsu[lr * XS_STR + 8 * n + 2 * tg + 1] = __float_as_uint(ev[2 * n + 1] * inv);
                }
            }
        }

        if (!last) {
            __syncthreads();   // rs complete
            // --- GEMM2: S[64x72] += r^T[64x128] @ xext[128x72] (n-split by nh) ---
            const int j0 = 16 * mg;
            #pragma unroll
            for (int kk = 0; kk < 16; kk++) {
                uint32_t afr[4];
                afr[0] = rsu[(8 * kk + tg) * XS_STR + j0 + g];
                afr[1] = rsu[(8 * kk + tg) * XS_STR + j0 + g + 8];
                afr[2] = rsu[(8 * kk + tg + 4) * XS_STR + j0 + g];
                afr[3] = rsu[(8 * kk + tg + 4) * XS_STR + j0 + g + 8];
                #pragma unroll
                for (int n = 0; n < 5; n++) {
                    if (n < ntiles) {
                        uint32_t b0 = xsu[(8 * kk + tg) * XS_STR + 8 * (nbase + n) + g];
                        uint32_t b1 = xsu[(8 * kk + tg + 4) * XS_STR + 8 * (nbase + n) + g];
                        mma_tf32(sfr[n], afr, b0, b1);
                    }
                }
            }
        }
    }

    if (!last) {
        // GEMM2 epilogue: atomics to g_S / g_rsum
        float* gs = g_S + it * KC * DL;
        const int j0 = 16 * mg;
        #pragma unroll
        for (int h = 0; h < 2; h++) {
            const int j = j0 + g + 8 * h;
            #pragma unroll
            for (int n = 0; n < 5; n++) {
                const int nn = nbase + n;
                if (n < ntiles && nn < 8) {
                    atomicAdd(&gs[j * DL + 8 * nn + 2 * tg],     sfr[n][2 * h]);
                    atomicAdd(&gs[j * DL + 8 * nn + 2 * tg + 1], sfr[n][2 * h + 1]);
                }
            }
            if (nh == 1 && tg == 0)   // n==8: ones column = rsum
                atomicAdd(&g_rsum[it * KC + j], sfr[4][2 * h]);
        }
    } else {
        float v = lossacc;
        #pragma unroll
        for (int o = 16; o > 0; o >>= 1) v += __shfl_down_sync(0xffffffffu, v, o);
        __syncthreads();
        if (lane == 0) red[wid] = v;
        __syncthreads();
        if (tid == 0) {
            float sum = 0.0f;
            #pragma unroll
            for (int w = 0; w < 8; w++) sum += red[w];
            atomicAdd(&g_loss, sum);
        }
    }

    // --- fused decoder-loss chunk: 4x unrolled batched loads for MLP,
    //     __ldcs so the X/decoding stream doesn't evict enc from L2 ---
    {
        const int S = gridDim.x * NTH;
        float a0 = 0.0f, a1 = 0.0f, a2 = 0.0f, a3 = 0.0f;
        int i = d_start + blockIdx.x * NTH + tid;
        for (; i + 3 * S < d_end; i += 4 * S) {
            float4 x0 = __ldcs(&X4[i]);
            float4 x1 = __ldcs(&X4[i + S]);
            float4 x2 = __ldcs(&X4[i + 2 * S]);
            float4 x3 = __ldcs(&X4[i + 3 * S]);
            float4 d0 = __ldcs(&D4[i]);
            float4 d1 = __ldcs(&D4[i + S]);
            float4 d2 = __ldcs(&D4[i + 2 * S]);
            float4 d3 = __ldcs(&D4[i + 3 * S]);
            float t;
            t = x0.x - d0.x; a0 += t * t;  t = x0.y - d0.y; a0 += t * t;
            t = x0.z - d0.z; a0 += t * t;  t = x0.w - d0.w; a0 += t * t;
            t = x1.x - d1.x; a1 += t * t;  t = x1.y - d1.y; a1 += t * t;
            t = x1.z - d1.z; a1 += t * t;  t = x1.w - d1.w; a1 += t * t;
            t = x2.x - d2.x; a2 += t * t;  t = x2.y - d2.y; a2 += t * t;
            t = x2.z - d2.z; a2 += t * t;  t = x2.w - d2.w; a2 += t * t;
            t = x3.x - d3.x; a3 += t * t;  t = x3.y - d3.y; a3 += t * t;
            t = x3.z - d3.z; a3 += t * t;  t = x3.w - d3.w; a3 += t * t;
        }
        float acc = (a0 + a1) + (a2 + a3);
        for (; i < d_end; i += S) {
            float4 x = __ldcs(&X4[i]), d = __ldcs(&D4[i]);
            float a = x.x - d.x, b = x.y - d.y, c = x.z - d.z, e = x.w - d.w;
            acc += a * a + b * b;
            acc += c * c + e * e;
        }
        #pragma unroll
        for (int o = 16; o > 0; o >>= 1) acc += __shfl_down_sync(0xffffffffu, acc, o);
        __syncthreads();
        if (lane == 0) red[wid] = acc;
        __syncthreads();
        if (tid == 0) {
            float sum = 0.0f;
            #pragma unroll
            for (int w = 0; w < 8; w++) sum += red[w];
            atomicAdd(&g_dec, sum);
        }
    }
}

// ---------------------------------------------------------------------------
__global__ void final_kernel(float* out, int nX, int N) {
    out[0] = g_dec / (float)nX + ALPHA_C * (g_loss / (float)N);
}

// ---------------------------------------------------------------------------
extern "C" void kernel_launch(void* const* d_in, const int* in_sizes, int n_in,
                              void* d_out, int out_size) {
    const float* X   = (const float*)d_in[0];
    const float* enc = (const float*)d_in[1];
    const float* dec = (const float*)d_in[2];
    const int nX = in_sizes[0];
    const int N  = in_sizes[1] / DL;
    const int n4 = nX / 4;

    cudaFuncSetAttribute(main_kernel, cudaFuncAttributeMaxDynamicSharedMemorySize, SMEM_BYTES);

    init_kernel<<<40, 1024>>>();

    const int blocks = N / RPB;   // 256
    const int chunk = (n4 + NIT - 1) / NIT;
    for (int it = 0; it < NIT; it++) {
        int ds = it * chunk;
        int de = (it == NIT - 1) ? n4 : ds + chunk;
        main_kernel<<<blocks, NTH, SMEM_BYTES>>>(
            enc, (const float4*)X, (const float4*)dec, ds, de, N, it);
    }
    final_kernel<<<1, 1>>>((float*)d_out, nX, N);
}

// round 12
// speedup vs baseline: 1.2846x; 1.2004x over previous
#include <cuda_runtime.h>
#include <cuda_bf16.h>
#include <cstdint>

// Problem constants: N=65536, D_LAT=64, K=64, D_DATA=512
#define KC      64
#define DL      64
#define RPT     128              // rows per subtile
#define NSUB    2
#define RPB     (RPT * NSUB)     // 256 rows per CTA
#define NTH     256              // 8 warps
#define NIT     10
#define ALPHA_C 0.001f
#define EPS_C   1e-8f
#define POS_INF_F (__int_as_float(0x7f800000))

// smem u32 offsets
#define XSH_STR 36               // x col-pair layout: [row][pair], GEMM1 A
#define XSB_STR 72               // x row-pair layout: [rowpair][col 0..71], GEMM2 B (+ones col 64)
#define RSB_STR 72               // r row-pair layout: [rowpair][j],     GEMM2 A
#define OFF_XSH 0                                // 128*36 = 4608
#define OFF_XSB (OFF_XSH + RPT * XSH_STR)        // 4608,  64*72 = 4608
#define OFF_RSB (OFF_XSB + (RPT/2) * XSB_STR)    // 9216,  64*72 = 4608
#define OFF_CFF (OFF_RSB + (RPT/2) * RSB_STR)    // 13824, 4*8*32 uint2 = 2048 u32
#define OFF_C2  (OFF_CFF + 2048)                 // 15872
#define OFF_X2  (OFF_C2 + KC)                    // 15936
#define OFF_RED (OFF_X2 + RPT)                   // 16064
#define SMEM_U32 (OFF_RED + 32)                  // 16096
#define SMEM_BYTES (SMEM_U32 * 4)                // 64384 B -> 2 CTAs/SM

// Per-iteration accumulation buffers (iter t writes buf t, iter t+1 reads it)
__device__ float g_S[(NIT - 1) * KC * DL];
__device__ float g_rsum[(NIT - 1) * KC];
__device__ float g_loss;
__device__ float g_dec;

// ---------------------------------------------------------------------------
// pack two f32 -> bf16x2 (lo = first arg in low 16 bits)
__device__ __forceinline__ uint32_t pack_bf2(float lo, float hi) {
    uint32_t u;
    asm("cvt.rn.bf16x2.f32 %0, %1, %2;" : "=r"(u) : "f"(hi), "f"(lo));
    return u;
}

// D (f32) += A (bf16) * B (bf16), m16n8k16
__device__ __forceinline__ void mma_bf16(float* d, const uint32_t* a, uint32_t b0, uint32_t b1) {
    asm volatile(
        "mma.sync.aligned.m16n8k16.row.col.f32.bf16.bf16.f32 "
        "{%0,%1,%2,%3}, {%4,%5,%6,%7}, {%8,%9}, {%0,%1,%2,%3};"
        : "+f"(d[0]), "+f"(d[1]), "+f"(d[2]), "+f"(d[3])
        : "r"(a[0]), "r"(a[1]), "r"(a[2]), "r"(a[3]), "r"(b0), "r"(b1));
}

// ---------------------------------------------------------------------------
__global__ void init_kernel() {
    int t = blockIdx.x * blockDim.x + threadIdx.x;
    int total = (NIT - 1) * KC * DL;
    for (int i = t; i < total; i += gridDim.x * blockDim.x) g_S[i] = 0.0f;
    if (t < (NIT - 1) * KC) g_rsum[t] = 0.0f;
    if (t == 0) { g_loss = 0.0f; g_dec = 0.0f; }
}

// ---------------------------------------------------------------------------
// Main fused iteration kernel (mma.sync bf16 m16n8k16) + decoder-loss chunk
// ---------------------------------------------------------------------------
extern __shared__ uint32_t su[];

__global__ __launch_bounds__(NTH, 2)
void main_kernel(const float* __restrict__ enc,
                 const float4* __restrict__ X4, const float4* __restrict__ D4,
                 int d_start, int d_end, int N, int it) {
    uint32_t* xsh = su + OFF_XSH;
    uint32_t* xsb = su + OFF_XSB;
    uint32_t* rsb = su + OFF_RSB;
    uint2*    cff = (uint2*)(su + OFF_CFF);   // [(kk*8+n)*32 + lane] = (b0,b1)
    float*    c2s = (float*)(su + OFF_C2);
    float*    x2s = (float*)(su + OFF_X2);
    float*    red = (float*)(su + OFF_RED);

    const int tid  = threadIdx.x;
    const int wid  = tid >> 5;
    const int lane = tid & 31;
    const int g    = lane >> 2;     // groupID
    const int tg   = lane & 3;      // threadID_in_group
    const bool last = (it == NIT - 1);
    const int row_base = blockIdx.x * RPB;

    // --- C setup: C[j][d] from prev-iter S/rsum (or enc rows for it=0),
    //     packed into bf16x2 B-fragment layout (cff); c2 in f32 ---
    {
        const int j = tid >> 2, h = tid & 3;   // 16 cols per thread: cols 16h..16h+15; kk = h
        const int n = j >> 3, gg = j & 7;      // j = 8n + gg
        float part = 0.0f;
        float invd = 0.0f;
        if (it > 0) invd = 1.0f / (g_rsum[(it - 1) * KC + j] + EPS_C);
        const float* src = (it == 0) ? (enc + j * DL) : (g_S + (it - 1) * KC * DL + j * DL);
        float v[16];
        #pragma unroll
        for (int c = 0; c < 16; c++) {
            float x = src[16 * h + c];
            if (it > 0) x *= invd;
            part += x * x;
            v[c] = x;
        }
        #pragma unroll
        for (int t = 0; t < 4; t++) {
            uint2 bb;
            bb.x = pack_bf2(v[2 * t],     v[2 * t + 1]);      // k cols 16h+2t, +1
            bb.y = pack_bf2(v[2 * t + 8], v[2 * t + 9]);      // k cols 16h+2t+8, +9
            cff[(h * 8 + n) * 32 + 4 * gg + t] = bb;
        }
        part += __shfl_xor_sync(0xffffffffu, part, 1);
        part += __shfl_xor_sync(0xffffffffu, part, 2);
        if (h == 0) c2s[j] = part;

        // ones/zero columns of xsb (cols 64..71), constant across subtiles
        if (tid < RPT / 2) {
            uint4 o; o.x = 0x3F803F80u; o.y = 0; o.z = 0; o.w = 0;
            *(uint4*)(xsb + tid * XSB_STR + 64) = o;
            uint4 z; z.x = 0; z.y = 0; z.z = 0; z.w = 0;
            *(uint4*)(xsb + tid * XSB_STR + 68) = z;
        }
    }

    // GEMM2 accumulators: warp (mg = wid&3, nh = wid>>2)
    const int mg = wid & 3, nh = wid >> 2;
    const int nbase = nh * 4, ntiles = nh ? 5 : 4;
    float sfr[5][4];
    #pragma unroll
    for (int n = 0; n < 5; n++)
        #pragma unroll
        for (int q = 0; q < 4; q++) sfr[n][q] = 0.0f;

    float lossacc = 0.0f;

    for (int s = 0; s < NSUB; s++) {
        const int row0 = row_base + s * RPT;
        __syncthreads();   // cff/c2/ones ready (s=0); xsh/xsb/rsb free (s>0)

        // --- load x rows (2 threads per row), pack bf16, x2 (f32) ---
        {
            const int row = tid >> 1, half = tid & 1;
            const float4* rowp = (const float4*)(enc + (size_t)(row0 + row) * DL) + 8 * half;
            float x2 = 0.0f;
            uint32_t pk[16];
            #pragma unroll
            for (int q = 0; q < 8; q++) {
                float4 v = rowp[q];
                x2 += v.x * v.x + v.y * v.y;
                x2 += v.z * v.z + v.w * v.w;
                pk[2 * q]     = pack_bf2(v.x, v.y);
                pk[2 * q + 1] = pack_bf2(v.z, v.w);
            }
            // xsh: [row][pair], pairs along cols (GEMM1 A)
            #pragma unroll
            for (int q = 0; q < 4; q++) {
                uint4 w; w.x = pk[4 * q]; w.y = pk[4 * q + 1]; w.z = pk[4 * q + 2]; w.w = pk[4 * q + 3];
                *(uint4*)(xsh + row * XSH_STR + 16 * half + 4 * q) = w;
            }
            // xsb: [rowpair][col] via packed shfl + byte_perm (GEMM2 B)
            uint32_t prt[16];
            #pragma unroll
            for (int p = 0; p < 16; p++)
                prt[p] = __shfl_down_sync(0xffffffffu, pk[p], 2);   // partner = next row, same half
            if ((tid & 2) == 0) {
                const int rp = row >> 1;
                #pragma unroll
                for (int q = 0; q < 8; q++) {
                    uint4 w;
                    w.x = __byte_perm(pk[2 * q],     prt[2 * q],     0x5410);  // col 4q+0
                    w.y = __byte_perm(pk[2 * q],     prt[2 * q],     0x7632);  // col 4q+1
                    w.z = __byte_perm(pk[2 * q + 1], prt[2 * q + 1], 0x5410);  // col 4q+2
                    w.w = __byte_perm(pk[2 * q + 1], prt[2 * q + 1], 0x7632);  // col 4q+3
                    *(uint4*)(xsb + rp * XSB_STR + 32 * half + 4 * q) = w;
                }
            }
            x2 += __shfl_xor_sync(0xffffffffu, x2, 1);
            if (half == 0) x2s[row] = x2;
        }
        __syncthreads();

        // --- GEMM1: warp's D[16x64] = x[16x64] @ C^T, bf16 k16 steps ---
        const int wr0 = wid * 16;
        float dfr[8][4];
        #pragma unroll
        for (int n = 0; n < 8; n++)
            #pragma unroll
            for (int q = 0; q < 4; q++) dfr[n][q] = 0.0f;

        #pragma unroll
        for (int kk = 0; kk < 4; kk++) {
            uint32_t afr[4];
            afr[0] = xsh[(wr0 + g)     * XSH_STR + 8 * kk + tg];
            afr[1] = xsh[(wr0 + g + 8) * XSH_STR + 8 * kk + tg];
            afr[2] = xsh[(wr0 + g)     * XSH_STR + 8 * kk + tg + 4];
            afr[3] = xsh[(wr0 + g + 8) * XSH_STR + 8 * kk + tg + 4];
            #pragma unroll
            for (int n = 0; n < 8; n++) {
                uint2 bb = cff[(kk * 8 + n) * 32 + lane];
                mma_bf16(dfr[n], afr, bb.x, bb.y);
            }
        }

        // --- epilogue: d2, softmax, write r (or loss) ---
        float c2v[16];
        {
            const float2* c2p = (const float2*)(c2s);
            #pragma unroll
            for (int n = 0; n < 8; n++) {
                float2 p = c2p[4 * n + tg];
                c2v[2 * n] = p.x; c2v[2 * n + 1] = p.y;
            }
        }
        #pragma unroll
        for (int h = 0; h < 2; h++) {
            const int lr = wr0 + 8 * h + g;
            const float x2v = x2s[lr];
            float d2v[16];
            float mn = POS_INF_F;
            #pragma unroll
            for (int n = 0; n < 8; n++) {
                float v0 = fmaxf(x2v + c2v[2 * n]     - 2.0f * dfr[n][2 * h],     0.0f);
                float v1 = fmaxf(x2v + c2v[2 * n + 1] - 2.0f * dfr[n][2 * h + 1], 0.0f);
                d2v[2 * n] = v0; d2v[2 * n + 1] = v1;
                mn = fminf(mn, fminf(v0, v1));
            }
            mn = fminf(mn, __shfl_xor_sync(0xffffffffu, mn, 1));
            mn = fminf(mn, __shfl_xor_sync(0xffffffffu, mn, 2));
            float Z = 0.0f, ed2 = 0.0f;
            float ev[16];
            #pragma unroll
            for (int q = 0; q < 16; q++) {
                float e = __expf(mn - d2v[q]);
                Z += e; ed2 += e * d2v[q];
                ev[q] = e;
            }
            Z += __shfl_xor_sync(0xffffffffu, Z, 1);
            Z += __shfl_xor_sync(0xffffffffu, Z, 2);
            const float inv = 1.0f / Z;
            if (last) {
                ed2 += __shfl_xor_sync(0xffffffffu, ed2, 1);
                ed2 += __shfl_xor_sync(0xffffffffu, ed2, 2);
                lossacc += 0.25f * ed2 * inv;   // quad holds 4 copies
            } else {
                // rsb: [rowpair][j] — even-g lanes pack (own row, partner row lr+1)
                #pragma unroll
                for (int n = 0; n < 8; n++) {
                    float r0 = ev[2 * n]     * inv;
                    float r1 = ev[2 * n + 1] * inv;
                    float p0 = __shfl_down_sync(0xffffffffu, r0, 4);
                    float p1 = __shfl_down_sync(0xffffffffu, r1, 4);
                    if ((g & 1) == 0) {
                        uint2 w;
                        w.x = pack_bf2(r0, p0);   // col 8n+2tg
                        w.y = pack_bf2(r1, p1);   // col 8n+2tg+1
                        *(uint2*)(rsb + (lr >> 1) * RSB_STR + 8 * n + 2 * tg) = w;
                    }
                }
            }
        }

        if (!last) {
            __syncthreads();   // rsb complete
            // --- GEMM2: S[64x72] += r^T[64x128] @ xext[128x72], bf16 k16 ---
            const int j0 = 16 * mg;
            #pragma unroll
            for (int kk = 0; kk < 8; kk++) {
                uint32_t afr[4];
                afr[0] = rsb[(8 * kk + tg)     * RSB_STR + j0 + g];
                afr[1] = rsb[(8 * kk + tg)     * RSB_STR + j0 + g + 8];
                afr[2] = rsb[(8 * kk + tg + 4) * RSB_STR + j0 + g];
                afr[3] = rsb[(8 * kk + tg + 4) * RSB_STR + j0 + g + 8];
                #pragma unroll
                for (int n = 0; n < 5; n++) {
                    if (n < ntiles) {
                        uint32_t b0 = xsb[(8 * kk + tg)     * XSB_STR + 8 * (nbase + n) + g];
                        uint32_t b1 = xsb[(8 * kk + tg + 4) * XSB_STR + 8 * (nbase + n) + g];
                        mma_bf16(sfr[n], afr, b0, b1);
                    }
                }
            }
        }
    }

    if (!last) {
        // GEMM2 epilogue: atomics to g_S / g_rsum
        float* gs = g_S + it * KC * DL;
        const int j0 = 16 * mg;
        #pragma unroll
        for (int h = 0; h < 2; h++) {
            const int j = j0 + g + 8 * h;
            #pragma unroll
            for (int n = 0; n < 5; n++) {
                const int nn = nbase + n;
                if (n < ntiles && nn < 8) {
                    atomicAdd(&gs[j * DL + 8 * nn + 2 * tg],     sfr[n][2 * h]);
                    atomicAdd(&gs[j * DL + 8 * nn + 2 * tg + 1], sfr[n][2 * h + 1]);
                }
            }
            if (nh == 1 && tg == 0)   // n-tile 8, col 64: ones column = rsum
                atomicAdd(&g_rsum[it * KC + j], sfr[4][2 * h]);
        }
    } else {
        float v = lossacc;
        #pragma unroll
        for (int o = 16; o > 0; o >>= 1) v += __shfl_down_sync(0xffffffffu, v, o);
        __syncthreads();
        if (lane == 0) red[wid] = v;
        __syncthreads();
        if (tid == 0) {
            float sum = 0.0f;
            #pragma unroll
            for (int w = 0; w < 8; w++) sum += red[w];
            atomicAdd(&g_loss, sum);
        }
    }

    // --- fused decoder-loss chunk (1/NIT of X/decoding), streaming ---
    {
        const int S = gridDim.x * NTH;
        float a0 = 0.0f, a1 = 0.0f, a2 = 0.0f, a3 = 0.0f;
        int i = d_start + blockIdx.x * NTH + tid;
        for (; i + 3 * S < d_end; i += 4 * S) {
            float4 x0 = __ldcs(&X4[i]);
            float4 x1 = __ldcs(&X4[i + S]);
            float4 x2 = __ldcs(&X4[i + 2 * S]);
            float4 x3 = __ldcs(&X4[i + 3 * S]);
            float4 d0 = __ldcs(&D4[i]);
            float4 d1 = __ldcs(&D4[i + S]);
            float4 d2 = __ldcs(&D4[i + 2 * S]);
            float4 d3 = __ldcs(&D4[i + 3 * S]);
            float t;
            t = x0.x - d0.x; a0 += t * t;  t = x0.y - d0.y; a0 += t * t;
            t = x0.z - d0.z; a0 += t * t;  t = x0.w - d0.w; a0 += t * t;
            t = x1.x - d1.x; a1 += t * t;  t = x1.y - d1.y; a1 += t * t;
            t = x1.z - d1.z; a1 += t * t;  t = x1.w - d1.w; a1 += t * t;
            t = x2.x - d2.x; a2 += t * t;  t = x2.y - d2.y; a2 += t * t;
            t = x2.z - d2.z; a2 += t * t;  t = x2.w - d2.w; a2 += t * t;
            t = x3.x - d3.x; a3 += t * t;  t = x3.y - d3.y; a3 += t * t;
            t = x3.z - d3.z; a3 += t * t;  t = x3.w - d3.w; a3 += t * t;
        }
        float acc = (a0 + a1) + (a2 + a3);
        for (; i < d_end; i += S) {
            float4 x = __ldcs(&X4[i]), d = __ldcs(&D4[i]);
            float a = x.x - d.x, b = x.y - d.y, c = x.z - d.z, e = x.w - d.w;
            acc += a * a + b * b;
            acc += c * c + e * e;
        }
        #pragma unroll
        for (int o = 16; o > 0; o >>= 1) acc += __shfl_down_sync(0xffffffffu, acc, o);
        __syncthreads();
        if (lane == 0) red[wid] = acc;
        __syncthreads();
        if (tid == 0) {
            float sum = 0.0f;
            #pragma unroll
            for (int w = 0; w < 8; w++) sum += red[w];
            atomicAdd(&g_dec, sum);
        }
    }
}

// ---------------------------------------------------------------------------
__global__ void final_kernel(float* out, int nX, int N) {
    out[0] = g_dec / (float)nX + ALPHA_C * (g_loss / (float)N);
}

// ---------------------------------------------------------------------------
extern "C" void kernel_launch(void* const* d_in, const int* in_sizes, int n_in,
                              void* d_out, int out_size) {
    const float* X   = (const float*)d_in[0];
    const float* enc = (const float*)d_in[1];
    const float* dec = (const float*)d_in[2];
    const int nX = in_sizes[0];
    const int N  = in_sizes[1] / DL;
    const int n4 = nX / 4;

    cudaFuncSetAttribute(main_kernel, cudaFuncAttributeMaxDynamicSharedMemorySize, SMEM_BYTES);

    init_kernel<<<40, 1024>>>();

    const int blocks = N / RPB;   // 256
    const int chunk = (n4 + NIT - 1) / NIT;
    for (int it = 0; it < NIT; it++) {
        int ds = it * chunk;
        int de = (it == NIT - 1) ? n4 : ds + chunk;
        main_kernel<<<blocks, NTH, SMEM_BYTES>>>(
            enc, (const float4*)X, (const float4*)dec, ds, de, N, it);
    }
    final_kernel<<<1, 1>>>((float*)d_out, nX, N);
}